// round 1
// baseline (speedup 1.0000x reference)
#include <cuda_runtime.h>
#include <cstdint>

// Problem constants
#define NN      100000
#define EE      1600000
#define DIN     128
#define CC      25000          // N / PF
#define PF      4
// bitmap over enc = csrc*CC + cdst  in [0, CC*CC) = [0, 625e6)
#define BM_WORDS 9765625u      // CC*CC / 64
#define WPB      2048          // words per count/emit block (256 thr * 8)
#define NBLK     4769          // ceil(BM_WORDS / WPB)

// Output layout in d_out (float32, flattened tuple concat):
//  x_new        [CC,128]  @ 0
//  new_pos      [CC,3]    @ 3,200,000
//  new_edge_idx [2,EE]    @ 3,275,000
//  new_edge_attr[EE,3]    @ 6,475,000
//  new_batch    [CC]      @ 11,275,000
#define XNEW_OFF  0
#define POS_OFF   3200000
#define IDX_OFF   3275000
#define ATTR_OFF  6475000
#define BATCH_OFF 11275000

static __device__ unsigned long long g_bitmap[BM_WORDS];
static __device__ float    g_cagg_x[CC * 128];
static __device__ float    g_cagg_e[CC * 4];
static __device__ float    g_newpos[CC * 3];
static __device__ unsigned g_blockSums[NBLK];
static __device__ unsigned g_blockOffs[NBLK];
static __device__ float    g_W1[128 * 128];
static __device__ float    g_W2[3 * 128];

// ---------------------------------------------------------------------------
__device__ __forceinline__ void red_add_v4(float* addr, float4 v) {
    asm volatile("red.global.add.v4.f32 [%0], {%1, %2, %3, %4};"
                 :: "l"(addr), "f"(v.x), "f"(v.y), "f"(v.z), "f"(v.w)
                 : "memory");
}

// ---------------------------------------------------------------------------
// K0: zero scratch + the output regions that need a zero tail
__global__ void k_zero(float* __restrict__ out) {
    size_t tid = (size_t)blockIdx.x * blockDim.x + threadIdx.x;
    size_t stride = (size_t)gridDim.x * blockDim.x;
    for (size_t i = tid; i < BM_WORDS; i += stride) g_bitmap[i] = 0ull;
    float4 z = make_float4(0.f, 0.f, 0.f, 0.f);
    float4* cx = (float4*)g_cagg_x;
    for (size_t i = tid; i < (size_t)CC * 32; i += stride) cx[i] = z;
    float4* ce = (float4*)g_cagg_e;
    for (size_t i = tid; i < (size_t)CC; i += stride) ce[i] = z;
    float4* oi = (float4*)(out + IDX_OFF);
    for (size_t i = tid; i < (size_t)(2 * EE) / 4; i += stride) oi[i] = z;
    float4* oa = (float4*)(out + ATTR_OFF);
    for (size_t i = tid; i < (size_t)(3 * EE) / 4; i += stride) oa[i] = z;
}

// ---------------------------------------------------------------------------
// KW: W1 = W_conv[:,16:144] @ W_gather  (128x128), W2 = W_edge[:,16:] @ W_gather
__global__ void k_weights(const float* __restrict__ Wc,
                          const float* __restrict__ We,
                          const float* __restrict__ Wg) {
    int j = threadIdx.x;        // 0..127 output col
    int i = blockIdx.x;         // 0..130
    if (i < 128) {
        float s = 0.f;
        #pragma unroll 8
        for (int k = 0; k < 128; k++) s += Wc[i * 144 + 16 + k] * Wg[k * 128 + j];
        g_W1[i * 128 + j] = s;
    } else {
        int r = i - 128;        // 0..2
        float s = 0.f;
        #pragma unroll 8
        for (int k = 0; k < 128; k++) s += We[r * 144 + 16 + k] * Wg[k * 128 + j];
        g_W2[r * 128 + j] = s;
    }
}

// ---------------------------------------------------------------------------
// KP: new_pos = mean of 4 node positions; new_batch = max of 4 (batch sorted)
__global__ void k_pos(const float* __restrict__ pos,
                      const int* __restrict__ batch,
                      float* __restrict__ out) {
    int c = blockIdx.x * blockDim.x + threadIdx.x;
    if (c >= CC) return;
    float s0 = 0.f, s1 = 0.f, s2 = 0.f;
    int bmax = -2147483647;
    #pragma unroll
    for (int i = 0; i < PF; i++) {
        int n = c * PF + i;
        s0 += pos[n * 3 + 0];
        s1 += pos[n * 3 + 1];
        s2 += pos[n * 3 + 2];
        int b = batch[n];
        bmax = b > bmax ? b : bmax;
    }
    s0 *= 0.25f; s1 *= 0.25f; s2 *= 0.25f;
    g_newpos[c * 3 + 0] = s0;
    g_newpos[c * 3 + 1] = s1;
    g_newpos[c * 3 + 2] = s2;
    out[POS_OFF + c * 3 + 0] = s0;
    out[POS_OFF + c * 3 + 1] = s1;
    out[POS_OFF + c * 3 + 2] = s2;
    out[BATCH_OFF + c] = (float)bmax;
}

// ---------------------------------------------------------------------------
// K1: per-edge scatter. One warp handles 32 edges:
//   - per-lane: edge_attr atomics into cluster accumulator + bitmap atomicOr
//   - loop: all 32 lanes cooperate on one edge's 128-float x row (LDG.128 + red.v4)
__global__ __launch_bounds__(256) void k_edges(const int* __restrict__ ei,
                                               const float* __restrict__ ea,
                                               const float* __restrict__ x) {
    int gtid = blockIdx.x * blockDim.x + threadIdx.x;
    int warp = gtid >> 5;
    int lane = gtid & 31;
    int e = warp * 32 + lane;          // EE % 32 == 0, no guard needed

    int src = ei[e];
    int dst = ei[EE + e];
    int c = dst >> 2;                  // dst / PF
    unsigned enc = (unsigned)(src >> 2) * (unsigned)CC + (unsigned)c;

    // bitmap set (unique cluster-pair detection)
    atomicOr(&g_bitmap[enc >> 6], 1ull << (enc & 63));

    // edge_attr cluster accumulation (3 scalar float reds)
    float a0 = ea[3 * e + 0], a1 = ea[3 * e + 1], a2 = ea[3 * e + 2];
    atomicAdd(&g_cagg_e[c * 4 + 0], a0);
    atomicAdd(&g_cagg_e[c * 4 + 1], a1);
    atomicAdd(&g_cagg_e[c * 4 + 2], a2);

    // x-row scatter: warp-cooperative, 512B per edge
    const float4* x4 = (const float4*)x;
    #pragma unroll 4
    for (int j = 0; j < 32; j++) {
        int s  = __shfl_sync(0xffffffffu, src, j);
        int cc = __shfl_sync(0xffffffffu, c, j);
        float4 v = __ldg(&x4[(size_t)s * 32 + lane]);
        red_add_v4(&g_cagg_x[(size_t)cc * 128 + lane * 4], v);
    }
}

// ---------------------------------------------------------------------------
// K2: per-block popcounts of the bitmap
__global__ void k_count() {
    int b = blockIdx.x, tid = threadIdx.x;
    size_t wbase = (size_t)b * WPB;
    int cnt = 0;
    #pragma unroll
    for (int i = 0; i < 8; i++) {
        size_t wi = wbase + (size_t)i * 256 + tid;
        if (wi < BM_WORDS) cnt += __popcll(g_bitmap[wi]);
    }
    #pragma unroll
    for (int o = 16; o > 0; o >>= 1) cnt += __shfl_down_sync(0xffffffffu, cnt, o);
    __shared__ int s[8];
    if ((tid & 31) == 0) s[tid >> 5] = cnt;
    __syncthreads();
    if (tid == 0) {
        int t = 0;
        #pragma unroll
        for (int i = 0; i < 8; i++) t += s[i];
        g_blockSums[b] = (unsigned)t;
    }
}

// ---------------------------------------------------------------------------
// K3: exclusive scan of 4769 block sums (single block)
__global__ void k_scan() {
    const int T = 512, PER = 10;   // 512*10 >= NBLK
    __shared__ unsigned s[T];
    int tid = threadIdx.x;
    unsigned local[PER];
    unsigned sum = 0;
    #pragma unroll
    for (int p = 0; p < PER; p++) {
        int idx = tid * PER + p;
        unsigned v = (idx < NBLK) ? g_blockSums[idx] : 0u;
        local[p] = sum;            // exclusive within-thread
        sum += v;
    }
    s[tid] = sum;
    __syncthreads();
    for (int o = 1; o < T; o <<= 1) {
        unsigned t = (tid >= o) ? s[tid - o] : 0u;
        __syncthreads();
        s[tid] += t;
        __syncthreads();
    }
    unsigned base = tid ? s[tid - 1] : 0u;
    #pragma unroll
    for (int p = 0; p < PER; p++) {
        int idx = tid * PER + p;
        if (idx < NBLK) g_blockOffs[idx] = base + local[p];
    }
}

// ---------------------------------------------------------------------------
__device__ __forceinline__ unsigned block_excl_scan256(unsigned v, unsigned* s_warp,
                                                       unsigned* total) {
    unsigned lane = threadIdx.x & 31, wid = threadIdx.x >> 5;
    unsigned x = v;
    #pragma unroll
    for (int o = 1; o < 32; o <<= 1) {
        unsigned y = __shfl_up_sync(0xffffffffu, x, o);
        if (lane >= o) x += y;
    }
    if (lane == 31) s_warp[wid] = x;
    __syncthreads();
    if (wid == 0) {
        unsigned t = (lane < 8) ? s_warp[lane] : 0u;
        #pragma unroll
        for (int o = 1; o < 8; o <<= 1) {
            unsigned y = __shfl_up_sync(0xffffffffu, t, o);
            if (lane >= o) t += y;
        }
        if (lane < 8) s_warp[lane] = t;
    }
    __syncthreads();
    unsigned warpBase = wid ? s_warp[wid - 1] : 0u;
    unsigned excl = warpBase + x - v;
    *total = s_warp[7];
    __syncthreads();               // safe reuse of s_warp next call
    return excl;
}

// K4: emit sorted-unique enc values + derived edge index / attr
__global__ void k_emit(float* __restrict__ out) {
    __shared__ unsigned s_warp[8];
    int b = blockIdx.x, tid = threadIdx.x;
    size_t wbase = (size_t)b * WPB;
    unsigned base = g_blockOffs[b];
    for (int i = 0; i < 8; i++) {
        size_t wi = wbase + (size_t)i * 256 + tid;
        unsigned long long w = (wi < BM_WORDS) ? g_bitmap[wi] : 0ull;
        unsigned cnt = (unsigned)__popcll(w);
        unsigned total;
        unsigned p = base + block_excl_scan256(cnt, s_warp, &total);
        while (w) {
            int bit = __ffsll((long long)w) - 1;
            w &= w - 1;
            unsigned v = (unsigned)wi * 64u + (unsigned)bit;
            unsigned sc = v / (unsigned)CC;
            unsigned dc = v % (unsigned)CC;
            out[IDX_OFF + p]      = (float)sc;
            out[IDX_OFF + EE + p] = (float)dc;
            out[ATTR_OFF + 3 * p + 0] = g_newpos[dc * 3 + 0] - g_newpos[sc * 3 + 0];
            out[ATTR_OFF + 3 * p + 1] = g_newpos[dc * 3 + 1] - g_newpos[sc * 3 + 1];
            out[ATTR_OFF + 3 * p + 2] = g_newpos[dc * 3 + 2] - g_newpos[sc * 3 + 2];
            p++;
        }
        base += total;
    }
}

// ---------------------------------------------------------------------------
// K5: x_new = (cagg_x @ W1 + cagg_e @ W2) / PF        [CC x 128]
// block: (128 cols, 2) threads, 16 cluster-rows per block; each thread: 8 rows x 1 col
__global__ __launch_bounds__(256) void k_gemm(float* __restrict__ out) {
    __shared__ float s_rows[16][128];
    int col = threadIdx.x;
    int ty = threadIdx.y;
    int r0 = blockIdx.x * 16;
    int t = ty * 128 + col;
    for (int i = t; i < 16 * 128; i += 256) {
        int rr = i >> 7, cc = i & 127;
        int gr = r0 + rr;
        s_rows[rr][cc] = (gr < CC) ? g_cagg_x[(size_t)gr * 128 + cc] : 0.f;
    }
    __syncthreads();
    float acc[8] = {0.f, 0.f, 0.f, 0.f, 0.f, 0.f, 0.f, 0.f};
    #pragma unroll 8
    for (int k = 0; k < 128; k += 4) {
        float w0 = __ldg(&g_W1[(k + 0) * 128 + col]);
        float w1 = __ldg(&g_W1[(k + 1) * 128 + col]);
        float w2 = __ldg(&g_W1[(k + 2) * 128 + col]);
        float w3 = __ldg(&g_W1[(k + 3) * 128 + col]);
        #pragma unroll
        for (int r = 0; r < 8; r++) {
            float4 cv = *(const float4*)&s_rows[ty * 8 + r][k];
            acc[r] += cv.x * w0 + cv.y * w1 + cv.z * w2 + cv.w * w3;
        }
    }
    float e0 = __ldg(&g_W2[0 * 128 + col]);
    float e1 = __ldg(&g_W2[1 * 128 + col]);
    float e2 = __ldg(&g_W2[2 * 128 + col]);
    #pragma unroll
    for (int r = 0; r < 8; r++) {
        int gr = r0 + ty * 8 + r;
        if (gr < CC) {
            float ce0 = g_cagg_e[gr * 4 + 0];
            float ce1 = g_cagg_e[gr * 4 + 1];
            float ce2 = g_cagg_e[gr * 4 + 2];
            float res = (acc[r] + ce0 * e0 + ce1 * e1 + ce2 * e2) * 0.25f;
            out[XNEW_OFF + (size_t)gr * 128 + col] = res;
        }
    }
}

// ---------------------------------------------------------------------------
extern "C" void kernel_launch(void* const* d_in, const int* in_sizes, int n_in,
                              void* d_out, int out_size) {
    const float* x   = (const float*)d_in[0];
    const float* pos = (const float*)d_in[1];
    const int*   ei  = (const int*)d_in[2];
    const float* ea  = (const float*)d_in[3];
    const int*   bat = (const int*)d_in[4];
    const float* Wc  = (const float*)d_in[5];
    const float* We  = (const float*)d_in[6];
    // d_in[7] = D_bloom (dead), d_in[9] = W_gattr (term cancels exactly)
    const float* Wg  = (const float*)d_in[8];
    float* out = (float*)d_out;

    k_zero<<<1024, 256>>>(out);
    k_weights<<<131, 128>>>(Wc, We, Wg);
    k_pos<<<(CC + 255) / 256, 256>>>(pos, bat, out);
    k_edges<<<EE / (32 * 8), 256>>>(ei, ea, x);
    k_count<<<NBLK, 256>>>();
    k_scan<<<1, 512>>>();
    k_emit<<<NBLK, 256>>>(out);
    dim3 gb(128, 2);
    k_gemm<<<(CC + 15) / 16, gb>>>(out);
}

// round 2
// speedup vs baseline: 1.0410x; 1.0410x over previous
#include <cuda_runtime.h>
#include <cstdint>

// Problem constants
#define NN      100000
#define EE      1600000
#define DIN     128
#define CC      25000          // N / PF
#define PF      4
// bitmap over enc = csrc*CC + cdst  in [0, CC*CC) = [0, 625e6)
#define BM_WORDS 9765625u      // CC*CC / 64
#define WPB      2048          // words per count/emit block (256 thr * 8)
#define NBLK     4769          // ceil(BM_WORDS / WPB)

// Output layout in d_out (float32, flattened tuple concat):
#define XNEW_OFF  0
#define POS_OFF   3200000
#define IDX_OFF   3275000
#define ATTR_OFF  6475000
#define BATCH_OFF 11275000

static __device__ unsigned long long g_bitmap[BM_WORDS];
static __device__ float    g_cagg_x[CC * 128];
static __device__ float    g_cagg_e[CC * 4];
static __device__ float    g_newpos[CC * 3];
static __device__ unsigned g_blockSums[NBLK];
static __device__ unsigned g_blockOffs[NBLK];
static __device__ float    g_W1[128 * 128];
static __device__ float    g_W2[3 * 128];
// edge binning by dst cluster
static __device__ unsigned g_hist[CC];
static __device__ unsigned g_start[CC];
static __device__ unsigned g_cursor[CC];
static __device__ int      g_binned_src[EE];

// ---------------------------------------------------------------------------
// K0: zero scratch + the output regions that need a zero tail
__global__ void k_zero(float* __restrict__ out) {
    size_t tid = (size_t)blockIdx.x * blockDim.x + threadIdx.x;
    size_t stride = (size_t)gridDim.x * blockDim.x;
    for (size_t i = tid; i < BM_WORDS; i += stride) g_bitmap[i] = 0ull;
    float4 z = make_float4(0.f, 0.f, 0.f, 0.f);
    float4* ce = (float4*)g_cagg_e;
    for (size_t i = tid; i < (size_t)CC; i += stride) ce[i] = z;
    for (size_t i = tid; i < (size_t)CC; i += stride) g_hist[i] = 0u;
    float4* oi = (float4*)(out + IDX_OFF);
    for (size_t i = tid; i < (size_t)(2 * EE) / 4; i += stride) oi[i] = z;
    float4* oa = (float4*)(out + ATTR_OFF);
    for (size_t i = tid; i < (size_t)(3 * EE) / 4; i += stride) oa[i] = z;
}

// ---------------------------------------------------------------------------
// K_misc: blocks [0,98) -> new_pos/new_batch ; blocks [98,229) -> weight GEMMs
__global__ void k_misc(const float* __restrict__ pos,
                       const int* __restrict__ batch,
                       const float* __restrict__ Wc,
                       const float* __restrict__ We,
                       const float* __restrict__ Wg,
                       float* __restrict__ out) {
    if (blockIdx.x < 98) {
        int c = blockIdx.x * 256 + threadIdx.x;
        if (c >= CC) return;
        float s0 = 0.f, s1 = 0.f, s2 = 0.f;
        int bmax = -2147483647;
        #pragma unroll
        for (int i = 0; i < PF; i++) {
            int n = c * PF + i;
            s0 += pos[n * 3 + 0];
            s1 += pos[n * 3 + 1];
            s2 += pos[n * 3 + 2];
            int b = batch[n];
            bmax = b > bmax ? b : bmax;
        }
        s0 *= 0.25f; s1 *= 0.25f; s2 *= 0.25f;
        g_newpos[c * 3 + 0] = s0;
        g_newpos[c * 3 + 1] = s1;
        g_newpos[c * 3 + 2] = s2;
        out[POS_OFF + c * 3 + 0] = s0;
        out[POS_OFF + c * 3 + 1] = s1;
        out[POS_OFF + c * 3 + 2] = s2;
        out[BATCH_OFF + c] = (float)bmax;
    } else {
        int i = blockIdx.x - 98;       // 0..130
        int j = threadIdx.x;
        if (j >= 128) return;
        if (i < 128) {
            float s = 0.f;
            #pragma unroll 8
            for (int k = 0; k < 128; k++) s += Wc[i * 144 + 16 + k] * Wg[k * 128 + j];
            g_W1[i * 128 + j] = s;
        } else {
            int r = i - 128;
            float s = 0.f;
            #pragma unroll 8
            for (int k = 0; k < 128; k++) s += We[r * 144 + 16 + k] * Wg[k * 128 + j];
            g_W2[r * 128 + j] = s;
        }
    }
}

// ---------------------------------------------------------------------------
// K_hist: per-edge pass 1: cluster histogram + bitmap set + edge_attr atomics
__global__ __launch_bounds__(256) void k_hist(const int* __restrict__ ei,
                                              const float* __restrict__ ea) {
    int e = blockIdx.x * 256 + threadIdx.x;
    if (e >= EE) return;
    int src = ei[e];
    int dst = ei[EE + e];
    int c = dst >> 2;
    unsigned enc = (unsigned)(src >> 2) * (unsigned)CC + (unsigned)c;
    atomicOr(&g_bitmap[enc >> 6], 1ull << (enc & 63));
    atomicAdd(&g_hist[c], 1u);
    float a0 = ea[3 * e + 0], a1 = ea[3 * e + 1], a2 = ea[3 * e + 2];
    atomicAdd(&g_cagg_e[c * 4 + 0], a0);
    atomicAdd(&g_cagg_e[c * 4 + 1], a1);
    atomicAdd(&g_cagg_e[c * 4 + 2], a2);
}

// ---------------------------------------------------------------------------
// K_scanC: exclusive scan of 25000 cluster counts (single block)
__global__ void k_scanC() {
    const int T = 1024, PER = 25;     // 1024*25 >= CC
    __shared__ unsigned s[T];
    int tid = threadIdx.x;
    unsigned local[PER];
    unsigned sum = 0;
    #pragma unroll
    for (int p = 0; p < PER; p++) {
        int idx = tid * PER + p;
        unsigned v = (idx < CC) ? g_hist[idx] : 0u;
        local[p] = sum;
        sum += v;
    }
    s[tid] = sum;
    __syncthreads();
    for (int o = 1; o < T; o <<= 1) {
        unsigned t = (tid >= o) ? s[tid - o] : 0u;
        __syncthreads();
        s[tid] += t;
        __syncthreads();
    }
    unsigned base = tid ? s[tid - 1] : 0u;
    #pragma unroll
    for (int p = 0; p < PER; p++) {
        int idx = tid * PER + p;
        if (idx < CC) {
            unsigned st = base + local[p];
            g_start[idx] = st;
            g_cursor[idx] = st;
        }
    }
}

// ---------------------------------------------------------------------------
// K_fill: per-edge pass 2: place src node into its dst-cluster bin
__global__ __launch_bounds__(256) void k_fill(const int* __restrict__ ei) {
    int e = blockIdx.x * 256 + threadIdx.x;
    if (e >= EE) return;
    int src = ei[e];
    int dst = ei[EE + e];
    int c = dst >> 2;
    unsigned p = atomicAdd(&g_cursor[c], 1u);
    g_binned_src[p] = src;
}

// ---------------------------------------------------------------------------
// K_cluster: one warp per cluster; gather x rows of its bin, accumulate in
// registers (float4 per lane = 128 floats per warp), write row once.
__global__ __launch_bounds__(256) void k_cluster(const float* __restrict__ x) {
    int warp = (blockIdx.x * 256 + threadIdx.x) >> 5;
    int lane = threadIdx.x & 31;
    if (warp >= CC) return;
    unsigned base = g_start[warp];
    unsigned cnt = g_hist[warp];
    const float4* x4 = (const float4*)x;
    float4 acc = make_float4(0.f, 0.f, 0.f, 0.f);

    unsigned k = 0;
    for (; k + 32 <= cnt; k += 32) {
        int s = g_binned_src[base + k + lane];
        #pragma unroll
        for (int j = 0; j < 32; j++) {
            int sb = __shfl_sync(0xffffffffu, s, j);
            float4 v = __ldg(&x4[(size_t)sb * 32 + lane]);
            acc.x += v.x; acc.y += v.y; acc.z += v.z; acc.w += v.w;
        }
    }
    int rem = (int)(cnt - k);
    if (rem > 0) {
        int s = (lane < rem) ? g_binned_src[base + k + lane] : 0;
        for (int j = 0; j < rem; j++) {
            int sb = __shfl_sync(0xffffffffu, s, j);
            float4 v = __ldg(&x4[(size_t)sb * 32 + lane]);
            acc.x += v.x; acc.y += v.y; acc.z += v.z; acc.w += v.w;
        }
    }
    ((float4*)g_cagg_x)[(size_t)warp * 32 + lane] = acc;
}

// ---------------------------------------------------------------------------
// K2: per-block popcounts of the bitmap
__global__ void k_count() {
    int b = blockIdx.x, tid = threadIdx.x;
    size_t wbase = (size_t)b * WPB;
    int cnt = 0;
    #pragma unroll
    for (int i = 0; i < 8; i++) {
        size_t wi = wbase + (size_t)i * 256 + tid;
        if (wi < BM_WORDS) cnt += __popcll(g_bitmap[wi]);
    }
    #pragma unroll
    for (int o = 16; o > 0; o >>= 1) cnt += __shfl_down_sync(0xffffffffu, cnt, o);
    __shared__ int s[8];
    if ((tid & 31) == 0) s[tid >> 5] = cnt;
    __syncthreads();
    if (tid == 0) {
        int t = 0;
        #pragma unroll
        for (int i = 0; i < 8; i++) t += s[i];
        g_blockSums[b] = (unsigned)t;
    }
}

// ---------------------------------------------------------------------------
// K3: exclusive scan of 4769 block sums (single block)
__global__ void k_scan() {
    const int T = 512, PER = 10;
    __shared__ unsigned s[T];
    int tid = threadIdx.x;
    unsigned local[PER];
    unsigned sum = 0;
    #pragma unroll
    for (int p = 0; p < PER; p++) {
        int idx = tid * PER + p;
        unsigned v = (idx < NBLK) ? g_blockSums[idx] : 0u;
        local[p] = sum;
        sum += v;
    }
    s[tid] = sum;
    __syncthreads();
    for (int o = 1; o < T; o <<= 1) {
        unsigned t = (tid >= o) ? s[tid - o] : 0u;
        __syncthreads();
        s[tid] += t;
        __syncthreads();
    }
    unsigned base = tid ? s[tid - 1] : 0u;
    #pragma unroll
    for (int p = 0; p < PER; p++) {
        int idx = tid * PER + p;
        if (idx < NBLK) g_blockOffs[idx] = base + local[p];
    }
}

// ---------------------------------------------------------------------------
__device__ __forceinline__ unsigned block_excl_scan256(unsigned v, unsigned* s_warp,
                                                       unsigned* total) {
    unsigned lane = threadIdx.x & 31, wid = threadIdx.x >> 5;
    unsigned x = v;
    #pragma unroll
    for (int o = 1; o < 32; o <<= 1) {
        unsigned y = __shfl_up_sync(0xffffffffu, x, o);
        if (lane >= o) x += y;
    }
    if (lane == 31) s_warp[wid] = x;
    __syncthreads();
    if (wid == 0) {
        unsigned t = (lane < 8) ? s_warp[lane] : 0u;
        #pragma unroll
        for (int o = 1; o < 8; o <<= 1) {
            unsigned y = __shfl_up_sync(0xffffffffu, t, o);
            if (lane >= o) t += y;
        }
        if (lane < 8) s_warp[lane] = t;
    }
    __syncthreads();
    unsigned warpBase = wid ? s_warp[wid - 1] : 0u;
    unsigned excl = warpBase + x - v;
    *total = s_warp[7];
    __syncthreads();
    return excl;
}

// K4: emit sorted-unique enc values + derived edge index / attr
__global__ void k_emit(float* __restrict__ out) {
    __shared__ unsigned s_warp[8];
    int b = blockIdx.x, tid = threadIdx.x;
    size_t wbase = (size_t)b * WPB;
    unsigned base = g_blockOffs[b];
    for (int i = 0; i < 8; i++) {
        size_t wi = wbase + (size_t)i * 256 + tid;
        unsigned long long w = (wi < BM_WORDS) ? g_bitmap[wi] : 0ull;
        unsigned cnt = (unsigned)__popcll(w);
        unsigned total;
        unsigned p = base + block_excl_scan256(cnt, s_warp, &total);
        while (w) {
            int bit = __ffsll((long long)w) - 1;
            w &= w - 1;
            unsigned v = (unsigned)wi * 64u + (unsigned)bit;
            unsigned sc = v / (unsigned)CC;
            unsigned dc = v % (unsigned)CC;
            out[IDX_OFF + p]      = (float)sc;
            out[IDX_OFF + EE + p] = (float)dc;
            out[ATTR_OFF + 3 * p + 0] = g_newpos[dc * 3 + 0] - g_newpos[sc * 3 + 0];
            out[ATTR_OFF + 3 * p + 1] = g_newpos[dc * 3 + 1] - g_newpos[sc * 3 + 1];
            out[ATTR_OFF + 3 * p + 2] = g_newpos[dc * 3 + 2] - g_newpos[sc * 3 + 2];
            p++;
        }
        base += total;
    }
}

// ---------------------------------------------------------------------------
// K5: x_new = (cagg_x @ W1 + cagg_e @ W2) / PF        [CC x 128]
__global__ __launch_bounds__(256) void k_gemm(float* __restrict__ out) {
    __shared__ float s_rows[16][128];
    int col = threadIdx.x;
    int ty = threadIdx.y;
    int r0 = blockIdx.x * 16;
    int t = ty * 128 + col;
    for (int i = t; i < 16 * 128; i += 256) {
        int rr = i >> 7, cc = i & 127;
        int gr = r0 + rr;
        s_rows[rr][cc] = (gr < CC) ? g_cagg_x[(size_t)gr * 128 + cc] : 0.f;
    }
    __syncthreads();
    float acc[8] = {0.f, 0.f, 0.f, 0.f, 0.f, 0.f, 0.f, 0.f};
    #pragma unroll 8
    for (int k = 0; k < 128; k += 4) {
        float w0 = __ldg(&g_W1[(k + 0) * 128 + col]);
        float w1 = __ldg(&g_W1[(k + 1) * 128 + col]);
        float w2 = __ldg(&g_W1[(k + 2) * 128 + col]);
        float w3 = __ldg(&g_W1[(k + 3) * 128 + col]);
        #pragma unroll
        for (int r = 0; r < 8; r++) {
            float4 cv = *(const float4*)&s_rows[ty * 8 + r][k];
            acc[r] += cv.x * w0 + cv.y * w1 + cv.z * w2 + cv.w * w3;
        }
    }
    float e0 = __ldg(&g_W2[0 * 128 + col]);
    float e1 = __ldg(&g_W2[1 * 128 + col]);
    float e2 = __ldg(&g_W2[2 * 128 + col]);
    #pragma unroll
    for (int r = 0; r < 8; r++) {
        int gr = r0 + ty * 8 + r;
        if (gr < CC) {
            float ce0 = g_cagg_e[gr * 4 + 0];
            float ce1 = g_cagg_e[gr * 4 + 1];
            float ce2 = g_cagg_e[gr * 4 + 2];
            float res = (acc[r] + ce0 * e0 + ce1 * e1 + ce2 * e2) * 0.25f;
            out[XNEW_OFF + (size_t)gr * 128 + col] = res;
        }
    }
}

// ---------------------------------------------------------------------------
extern "C" void kernel_launch(void* const* d_in, const int* in_sizes, int n_in,
                              void* d_out, int out_size) {
    const float* x   = (const float*)d_in[0];
    const float* pos = (const float*)d_in[1];
    const int*   ei  = (const int*)d_in[2];
    const float* ea  = (const float*)d_in[3];
    const int*   bat = (const int*)d_in[4];
    const float* Wc  = (const float*)d_in[5];
    const float* We  = (const float*)d_in[6];
    const float* Wg  = (const float*)d_in[8];
    float* out = (float*)d_out;

    k_zero<<<2048, 256>>>(out);
    k_misc<<<229, 256>>>(pos, bat, Wc, We, Wg, out);
    k_hist<<<EE / 256, 256>>>(ei, ea);
    k_scanC<<<1, 1024>>>();
    k_fill<<<EE / 256, 256>>>(ei);
    k_cluster<<<(CC * 32 + 255) / 256, 256>>>(x);
    k_count<<<NBLK, 256>>>();
    k_scan<<<1, 512>>>();
    k_emit<<<NBLK, 256>>>(out);
    dim3 gb(128, 2);
    k_gemm<<<(CC + 15) / 16, gb>>>(out);
}